// round 3
// baseline (speedup 1.0000x reference)
#include <cuda_runtime.h>
#include <math.h>

#define Hdim 512
#define G4   2048
#define NB   256      // B*U lstm lanes
#define LT   64       // timesteps
#define BB   8
#define UU   32
#define SS   2048
#define EE   128
#define NNODE 33      // U+1

typedef unsigned long long u64;

__device__ __forceinline__ u64 pk2(float lo, float hi){
  u64 r; asm("mov.b64 %0, {%1,%2};" : "=l"(r) : "r"(__float_as_uint(lo)), "r"(__float_as_uint(hi))); return r;
}
__device__ __forceinline__ u64 fma2(u64 a, u64 b, u64 c){
  u64 d; asm("fma.rn.f32x2 %0, %1, %2, %3;" : "=l"(d) : "l"(a), "l"(b), "l"(c)); return d;
}
__device__ __forceinline__ void upk2(u64 v, float& lo, float& hi){
  unsigned l_, h_; asm("mov.b64 {%0,%1}, %2;" : "=r"(l_), "=r"(h_) : "l"(v));
  lo = __uint_as_float(l_); hi = __uint_as_float(h_);
}

// ---------------- scratch (device globals; no allocations allowed) ----------
__device__ float g_x  [(size_t)LT*NB*Hdim];   // embedded inputs, [t*256+n][h]
__device__ float g_gx [(size_t)LT*NB*G4];     // x @ W_ih + b,  [t*256+n][4H]
__device__ float g_ys [(size_t)LT*NB*Hdim];   // h per step,    [t*256+n][h]
__device__ float g_h  [2][NB*Hdim];           // double-buffered hidden state
__device__ float g_c  [NB*Hdim];              // cell state (in-place)
__device__ float g_nodes[BB*NNODE*Hdim];
__device__ float g_msg  [(size_t)BB*EE*Hdim];
__device__ float g_agg  [BB*NNODE*Hdim];
__device__ float g_new  [BB*NNODE*Hdim];

// ---------------- output offsets (pytree flatten order) ---------------------
#define OFF_ENCH 0
#define OFF_ENCC 4096
#define OFF_MB   8192
#define OFF_LEN1 (8192 + 8388608)            // 8396800
#define OFF_MBU  (OFF_LEN1 + 8)              // 8396808
#define OFF_LEN2 (OFF_MBU + 8388608)         // 16785416
#define OFF_HIER (OFF_LEN2 + 8)              // 16785424

__device__ __forceinline__ float sigmf(float x){ return 1.0f/(1.0f+expf(-x)); }

// ---------------- init: zero h0, c0 ----------------------------------------
__global__ void k_zero(){
  int i = blockIdx.x*blockDim.x + threadIdx.x;
  if (i < NB*Hdim){ g_h[0][i] = 0.0f; g_c[i] = 0.0f; }
}

// ---------------- embedding gather -----------------------------------------
__global__ void k_embed(const int* __restrict__ src, const int* __restrict__ speaker,
                        const float* __restrict__ emb, const float* __restrict__ spkt){
  int row = blockIdx.x;            // t*256 + n
  int t = row >> 8, n = row & 255;
  int b = n >> 5, u = n & 31;
  int s = u*LT + t;
  int w  = src[s*BB + b];          // src (S,B,1)
  int sp = speaker[b*SS + s];      // speaker (B,S)
  const float* er = emb  + (size_t)w  * Hdim;
  const float* sr = spkt + (size_t)sp * Hdim;
  float* xr = g_x + (size_t)row * Hdim;
  for (int h = threadIdx.x; h < Hdim; h += blockDim.x)
    xr[h] = er[h] + sr[h];
}

// ---------------- Gx = x @ W_ih + b ; M=16384 N=2048 K=512 ------------------
// 128x128 tile, 256 threads, 8x8/thread via f32x2, double-buffered smem.
#define GXK 16
__global__ void __launch_bounds__(256) k_gx_gemm(const float* __restrict__ Wih,
                                                 const float* __restrict__ bias){
  __shared__ float As[2][GXK][132];   // [k][m] transposed, padded
  __shared__ float Bs[2][GXK][128];   // [k][n]
  int tid = threadIdx.x;
  int m0 = blockIdx.y*128, n0 = blockIdx.x*128;
  int tr = tid>>4, tc = tid&15;
  int ar = tid>>1, ak = (tid&1)<<3;
  int bk = tid>>4, bn = (tid&15)<<3;
  const float* Ap = g_x + (size_t)(m0+ar)*Hdim + ak;
  const float* Bp = Wih + (size_t)bk*G4 + n0 + bn;

  float4 ra0 = *(const float4*)Ap;
  float4 ra1 = *(const float4*)(Ap+4);
  float4 rb0 = *(const float4*)Bp;
  float4 rb1 = *(const float4*)(Bp+4);

  u64 acc[8][4];
  #pragma unroll
  for (int r=0;r<8;r++){ acc[r][0]=0ull; acc[r][1]=0ull; acc[r][2]=0ull; acc[r][3]=0ull; }

  int buf = 0;
  for (int k0 = 0; k0 < Hdim; k0 += GXK){
    As[buf][ak+0][ar]=ra0.x; As[buf][ak+1][ar]=ra0.y; As[buf][ak+2][ar]=ra0.z; As[buf][ak+3][ar]=ra0.w;
    As[buf][ak+4][ar]=ra1.x; As[buf][ak+5][ar]=ra1.y; As[buf][ak+6][ar]=ra1.z; As[buf][ak+7][ar]=ra1.w;
    *(float4*)&Bs[buf][bk][bn]   = rb0;
    *(float4*)&Bs[buf][bk][bn+4] = rb1;
    __syncthreads();
    if (k0 + GXK < Hdim){
      Ap += GXK; Bp += (size_t)GXK*G4;
      ra0 = *(const float4*)Ap; ra1 = *(const float4*)(Ap+4);
      rb0 = *(const float4*)Bp; rb1 = *(const float4*)(Bp+4);
    }
    #pragma unroll
    for (int kk=0; kk<GXK; kk++){
      float4 a0 = *(float4*)&As[buf][kk][tr<<3];
      float4 a1 = *(float4*)&As[buf][kk][(tr<<3)+4];
      u64 b01 = *(u64*)&Bs[buf][kk][tc<<3];
      u64 b23 = *(u64*)&Bs[buf][kk][(tc<<3)+2];
      u64 b45 = *(u64*)&Bs[buf][kk][(tc<<3)+4];
      u64 b67 = *(u64*)&Bs[buf][kk][(tc<<3)+6];
      float av[8] = {a0.x,a0.y,a0.z,a0.w,a1.x,a1.y,a1.z,a1.w};
      #pragma unroll
      for (int r=0;r<8;r++){
        u64 ad = pk2(av[r], av[r]);
        acc[r][0]=fma2(ad,b01,acc[r][0]);
        acc[r][1]=fma2(ad,b23,acc[r][1]);
        acc[r][2]=fma2(ad,b45,acc[r][2]);
        acc[r][3]=fma2(ad,b67,acc[r][3]);
      }
    }
    buf ^= 1;
  }
  int mrow = m0 + (tr<<3);
  int ncol = n0 + (tc<<3);
  float bsv[8];
  #pragma unroll
  for (int c=0;c<8;c++) bsv[c] = bias[ncol+c];
  #pragma unroll
  for (int r=0;r<8;r++){
    float o[8];
    upk2(acc[r][0], o[0], o[1]); upk2(acc[r][1], o[2], o[3]);
    upk2(acc[r][2], o[4], o[5]); upk2(acc[r][3], o[6], o[7]);
    float4 v0 = make_float4(o[0]+bsv[0], o[1]+bsv[1], o[2]+bsv[2], o[3]+bsv[3]);
    float4 v1 = make_float4(o[4]+bsv[4], o[5]+bsv[5], o[6]+bsv[6], o[7]+bsv[7]);
    *(float4*)&g_gx[(size_t)(mrow+r)*G4 + ncol]   = v0;
    *(float4*)&g_gx[(size_t)(mrow+r)*G4 + ncol+4] = v1;
  }
}

// ---------------- fused LSTM step -------------------------------------------
// CTA: 32 rows x 32 hidden cols (x4 gates). grid (16 jtiles, 8 mtiles) = 128 CTAs.
// thread: 4 rows x 1 hidden-pair x 4 gates = 16 f32x2 accumulators.
__global__ void __launch_bounds__(128) k_lstm_step(const float* __restrict__ Whh, int t){
  const float* hprev = g_h[t & 1];
  float*       hnext = g_h[(t+1) & 1];
  const float* gx = g_gx + (size_t)t*NB*G4;
  float*       ys = g_ys + (size_t)t*NB*Hdim;
  __shared__ float As[2][16][36];        // [k][row], padded
  __shared__ float Bs[2][16][16][4][2];  // [k][hiddenpair][gate][2]
  int tid = threadIdx.x;
  int j0 = blockIdx.x << 5;     // hidden tile base (32 cols)
  int m0 = blockIdx.y << 5;     // row tile base (32 rows)
  int rr = tid >> 4;            // 0..7 rowgroup (4 rows each)
  int jp = tid & 15;            // hidden pair 0..15
  int sar = tid >> 2, sak = (tid&3) << 2;              // A staging
  int sbk = tid >> 3, sbg = (tid>>1)&3, sbq = tid&1;   // B staging
  const float* Ap = hprev + (size_t)(m0 + sar)*Hdim + sak;
  const float* Bp = Whh + (size_t)sbk*G4 + sbg*Hdim + j0 + (sbq<<4);

  float4 ra = *(const float4*)Ap;
  float4 rb[4];
  #pragma unroll
  for (int f=0;f<4;f++) rb[f] = *(const float4*)(Bp + (f<<2));

  u64 acc[4][4];
  #pragma unroll
  for (int r=0;r<4;r++){ acc[r][0]=0ull; acc[r][1]=0ull; acc[r][2]=0ull; acc[r][3]=0ull; }

  int buf = 0;
  for (int k0 = 0; k0 < Hdim; k0 += 16){
    As[buf][sak+0][sar]=ra.x; As[buf][sak+1][sar]=ra.y;
    As[buf][sak+2][sar]=ra.z; As[buf][sak+3][sar]=ra.w;
    #pragma unroll
    for (int f=0;f<4;f++){
      int c = (sbq<<4) + (f<<2);
      Bs[buf][sbk][(c>>1)  ][sbg][0] = rb[f].x;
      Bs[buf][sbk][(c>>1)  ][sbg][1] = rb[f].y;
      Bs[buf][sbk][(c>>1)+1][sbg][0] = rb[f].z;
      Bs[buf][sbk][(c>>1)+1][sbg][1] = rb[f].w;
    }
    __syncthreads();
    if (k0 + 16 < Hdim){
      Ap += 16; Bp += (size_t)16*G4;
      ra = *(const float4*)Ap;
      #pragma unroll
      for (int f=0;f<4;f++) rb[f] = *(const float4*)(Bp + (f<<2));
    }
    #pragma unroll
    for (int kk=0; kk<16; kk++){
      float4 a = *(float4*)&As[buf][kk][rr<<2];
      u64 b0 = *(u64*)&Bs[buf][kk][jp][0][0];
      u64 b1 = *(u64*)&Bs[buf][kk][jp][1][0];
      u64 b2 = *(u64*)&Bs[buf][kk][jp][2][0];
      u64 b3 = *(u64*)&Bs[buf][kk][jp][3][0];
      float av[4] = {a.x,a.y,a.z,a.w};
      #pragma unroll
      for (int r=0;r<4;r++){
        u64 ad = pk2(av[r], av[r]);
        acc[r][0]=fma2(ad,b0,acc[r][0]);
        acc[r][1]=fma2(ad,b1,acc[r][1]);
        acc[r][2]=fma2(ad,b2,acc[r][2]);
        acc[r][3]=fma2(ad,b3,acc[r][3]);
      }
    }
    buf ^= 1;
  }
  int j = j0 + (jp<<1);
  #pragma unroll
  for (int r=0;r<4;r++){
    int n = m0 + (rr<<2) + r;
    float i0,i1,f0,f1,gg0,gg1,o0,o1;
    upk2(acc[r][0], i0, i1);
    upk2(acc[r][1], f0, f1);
    upk2(acc[r][2], gg0, gg1);
    upk2(acc[r][3], o0, o1);
    const float* gb = gx + (size_t)n*G4;
    float2 gi = *(const float2*)(gb + j);
    float2 gf = *(const float2*)(gb + Hdim + j);
    float2 gg = *(const float2*)(gb + 2*Hdim + j);
    float2 go = *(const float2*)(gb + 3*Hdim + j);
    i0+=gi.x; i1+=gi.y; f0+=gf.x; f1+=gf.y;
    gg0+=gg.x; gg1+=gg.y; o0+=go.x; o1+=go.y;
    float2 cv = *(float2*)(g_c + (size_t)n*Hdim + j);
    float c0 = sigmf(f0)*cv.x + sigmf(i0)*tanhf(gg0);
    float c1 = sigmf(f1)*cv.y + sigmf(i1)*tanhf(gg1);
    float h0 = sigmf(o0)*tanhf(c0);
    float h1 = sigmf(o1)*tanhf(c1);
    *(float2*)(g_c   + (size_t)n*Hdim + j) = make_float2(c0,c1);
    *(float2*)(hnext + (size_t)n*Hdim + j) = make_float2(h0,h1);
    *(float2*)(ys    + (size_t)n*Hdim + j) = make_float2(h0,h1);
  }
}

// ---------------- GNN: build nodes (utt_h rows + mean) ----------------------
__global__ void k_nodes(){
  int b = blockIdx.x, h = threadIdx.x;
  const float* last = g_ys + (size_t)(LT-1)*NB*Hdim;   // hT
  float s = 0.0f;
  for (int u = 0; u < UU; u++){
    float v = last[(size_t)(b*UU + u)*Hdim + h];
    g_nodes[(size_t)(b*NNODE + u)*Hdim + h] = v;
    s += v;
  }
  g_nodes[(size_t)(b*NNODE + UU)*Hdim + h] = s * (1.0f/UU);
}

// ---------------- per-edge message: msg = nodes[src] @ W_rel[rel] -----------
__global__ void __launch_bounds__(256) k_msg(const int* __restrict__ edge_src,
                                             const int* __restrict__ rels,
                                             const float* __restrict__ Wrel){
  int be = blockIdx.x;              // b*128 + e
  int b = be >> 7;
  int rel = rels[be];
  int es  = edge_src[be];
  __shared__ float xs[Hdim];
  int tid = threadIdx.x;
  xs[tid]     = g_nodes[(size_t)(b*NNODE + es)*Hdim + tid];
  xs[tid+256] = g_nodes[(size_t)(b*NNODE + es)*Hdim + tid + 256];
  __syncthreads();
  const float* W = Wrel + (size_t)rel*Hdim*Hdim;
  float a0 = 0.0f, a1 = 0.0f;
  for (int k = 0; k < Hdim; k++){
    float xv = xs[k];
    a0 += xv * W[(size_t)k*Hdim + tid];
    a1 += xv * W[(size_t)k*Hdim + tid + 256];
  }
  g_msg[(size_t)be*Hdim + tid]       = a0;
  g_msg[(size_t)be*Hdim + tid + 256] = a1;
}

// ---------------- deterministic segment-sum over edges ----------------------
__global__ void k_agg(const int* __restrict__ edge_dst){
  int bd = blockIdx.x;              // b*33 + d
  int b = bd / NNODE, d = bd % NNODE;
  int h = threadIdx.x;
  float a = 0.0f;
  for (int e = 0; e < EE; e++){
    if (edge_dst[b*EE + e] == d)
      a += g_msg[(size_t)(b*EE + e)*Hdim + h];
  }
  g_agg[(size_t)bd*Hdim + h] = a;
}

// ---------------- GNN output/gate fusion ------------------------------------
__global__ void __launch_bounds__(256) k_gnn(const float* __restrict__ Wself,
                                             const float* __restrict__ bg,
                                             const float* __restrict__ Wg1,
                                             const float* __restrict__ Wg2){
  int bd = blockIdx.x;
  __shared__ float nd[Hdim], ag[Hdim];
  int tid = threadIdx.x;
  nd[tid]     = g_nodes[(size_t)bd*Hdim + tid];
  nd[tid+256] = g_nodes[(size_t)bd*Hdim + tid + 256];
  ag[tid]     = g_agg[(size_t)bd*Hdim + tid];
  ag[tid+256] = g_agg[(size_t)bd*Hdim + tid + 256];
  __syncthreads();
  for (int jo = 0; jo < 2; jo++){
    int j = tid + jo*256;
    float s1 = 0.0f, s2 = 0.0f, s3 = 0.0f;
    for (int k = 0; k < Hdim; k++){
      float nv = nd[k], av = ag[k];
      s1 += nv * Wself[(size_t)k*Hdim + j];
      s2 += nv * Wg1  [(size_t)k*Hdim + j];
      s3 += av * Wg2  [(size_t)k*Hdim + j];
    }
    float outv = s1 + ag[j] + bg[j];
    outv = outv > 0.0f ? outv : 0.0f;
    float gate = sigmf(s2 + s3);
    g_new[(size_t)bd*Hdim + j] = gate*outv + (1.0f - gate)*nd[j];
  }
}

// ---------------- output writers --------------------------------------------
__global__ void k_out_small(float* __restrict__ dout, const int* __restrict__ lengths){
  int i = blockIdx.x*blockDim.x + threadIdx.x;   // 0..16383
  if (i < 4096){
    int b = i >> 9, h = i & 511;
    float v = g_new[(size_t)(b*NNODE + UU)*Hdim + h];   // global_reps
    dout[OFF_ENCH + i] = v;
    dout[OFF_ENCC + i] = v;
  }
  if (i < 8){
    float lv = (float)lengths[i];
    dout[OFF_LEN1 + i] = lv;
    dout[OFF_LEN2 + i] = lv;
  }
  dout[OFF_HIER + i] = (float)LT;   // hier_matrix == L everywhere
}

// fused memory_bank + mbu writer
__global__ void k_big_out(float* __restrict__ dout){
  size_t i = (size_t)blockIdx.x*blockDim.x + threadIdx.x;
  if (i >= (size_t)SS*BB*Hdim) return;
  int h = (int)(i & 511);
  int b = (int)((i >> 9) & 7);
  int s = (int)(i >> 12);
  int t = s & 63, u = s >> 6;
  dout[OFF_MB  + i] = g_ys[((size_t)t*NB + b*UU + u)*Hdim + h];
  dout[OFF_MBU + i] = g_new[(size_t)(b*NNODE + u)*Hdim + h];
}

// ---------------- driver -----------------------------------------------------
extern "C" void kernel_launch(void* const* d_in, const int* in_sizes, int n_in,
                              void* d_out, int out_size){
  const int*   src      = (const int*)  d_in[0];
  // d_in[1] = seg (unused by reference)
  const int*   speaker  = (const int*)  d_in[2];
  const int*   lengths  = (const int*)  d_in[3];
  const int*   edge_src = (const int*)  d_in[4];
  const int*   edge_dst = (const int*)  d_in[5];
  const int*   rels     = (const int*)  d_in[6];
  const float* emb      = (const float*)d_in[7];
  const float* spkt     = (const float*)d_in[8];
  const float* Wih      = (const float*)d_in[9];
  const float* Whh      = (const float*)d_in[10];
  const float* bl       = (const float*)d_in[11];
  const float* Wrel     = (const float*)d_in[12];
  const float* Wself    = (const float*)d_in[13];
  const float* bg       = (const float*)d_in[14];
  const float* Wg1      = (const float*)d_in[15];
  const float* Wg2      = (const float*)d_in[16];
  float* dout = (float*)d_out;

  k_zero<<<512, 256>>>();
  k_embed<<<LT*NB, 256>>>(src, speaker, emb, spkt);
  k_gx_gemm<<<dim3(G4/128, (LT*NB)/128), 256>>>(Wih, bl);
  for (int t = 0; t < LT; t++)
    k_lstm_step<<<dim3(16, 8), 128>>>(Whh, t);
  k_nodes<<<BB, 512>>>();
  k_msg<<<BB*EE, 256>>>(edge_src, rels, Wrel);
  k_agg<<<BB*NNODE, 512>>>(edge_dst);
  k_gnn<<<BB*NNODE, 256>>>(Wself, bg, Wg1, Wg2);
  k_out_small<<<64, 256>>>(dout, lengths);
  k_big_out<<<32768, 256>>>(dout);
}

// round 4
// speedup vs baseline: 2.0017x; 2.0017x over previous
#include <cuda_runtime.h>
#include <math.h>

#define Hdim 512
#define G4   2048
#define NB   256      // B*U lstm lanes
#define LT   64       // timesteps
#define BB   8
#define UU   32
#define SS   2048
#define EE   128
#define NNODE 33      // U+1
#define LSTM_GRID 128

typedef unsigned long long u64;

__device__ __forceinline__ u64 pk2(float lo, float hi){
  u64 r; asm("mov.b64 %0, {%1,%2};" : "=l"(r) : "r"(__float_as_uint(lo)), "r"(__float_as_uint(hi))); return r;
}
__device__ __forceinline__ u64 fma2(u64 a, u64 b, u64 c){
  u64 d; asm("fma.rn.f32x2 %0, %1, %2, %3;" : "=l"(d) : "l"(a), "l"(b), "l"(c)); return d;
}
__device__ __forceinline__ void upk2(u64 v, float& lo, float& hi){
  unsigned l_, h_; asm("mov.b64 {%0,%1}, %2;" : "=r"(l_), "=r"(h_) : "l"(v));
  lo = __uint_as_float(l_); hi = __uint_as_float(h_);
}

// ---------------- scratch (device globals; no allocations allowed) ----------
__device__ float g_x  [(size_t)LT*NB*Hdim];
__device__ float g_gx [(size_t)LT*NB*G4];
__device__ float g_ys [(size_t)LT*NB*Hdim];
__device__ float g_h  [2][NB*Hdim];
__device__ float g_nodes[BB*NNODE*Hdim];
__device__ float g_msg  [(size_t)BB*EE*Hdim];
__device__ float g_agg  [BB*NNODE*Hdim];
__device__ float g_new  [BB*NNODE*Hdim];
__device__ unsigned g_barrier;

// ---------------- output offsets (pytree flatten order) ---------------------
#define OFF_ENCH 0
#define OFF_ENCC 4096
#define OFF_MB   8192
#define OFF_LEN1 (8192 + 8388608)
#define OFF_MBU  (OFF_LEN1 + 8)
#define OFF_LEN2 (OFF_MBU + 8388608)
#define OFF_HIER (OFF_LEN2 + 8)

__device__ __forceinline__ float sigmf(float x){ return 1.0f/(1.0f+expf(-x)); }

// ---------------- init: zero h0, barrier ------------------------------------
__global__ void k_zero(){
  int i = blockIdx.x*blockDim.x + threadIdx.x;
  if (i < NB*Hdim){ g_h[0][i] = 0.0f; }
  if (i == 0) g_barrier = 0u;
}

// ---------------- embedding gather -----------------------------------------
__global__ void k_embed(const int* __restrict__ src, const int* __restrict__ speaker,
                        const float* __restrict__ emb, const float* __restrict__ spkt){
  int row = blockIdx.x;            // t*256 + n
  int t = row >> 8, n = row & 255;
  int b = n >> 5, u = n & 31;
  int s = u*LT + t;
  int w  = src[s*BB + b];
  int sp = speaker[b*SS + s];
  const float* er = emb  + (size_t)w  * Hdim;
  const float* sr = spkt + (size_t)sp * Hdim;
  float* xr = g_x + (size_t)row * Hdim;
  for (int h = threadIdx.x; h < Hdim; h += blockDim.x)
    xr[h] = er[h] + sr[h];
}

// ---------------- Gx = x @ W_ih + b ; M=16384 N=2048 K=512 (round-2 form) ---
__global__ void __launch_bounds__(256) k_gx_gemm(const float* __restrict__ Wih,
                                                 const float* __restrict__ bias){
  const int K = Hdim, N = G4;
  __shared__ float As[16][64];
  __shared__ float Bs[16][64];
  int tid = threadIdx.x;
  int m0 = blockIdx.y*64, n0 = blockIdx.x*64;
  int tr = tid>>4, tc = tid&15;
  int arow = tid>>2,  acol = (tid&3)<<2;
  int brow = tid>>4,  bcol = (tid&15)<<2;
  float acc[4][4] = {};
  for (int k0 = 0; k0 < K; k0 += 16){
    float4 av = *(const float4*)(g_x + (size_t)(m0+arow)*K + k0 + acol);
    As[acol  ][arow] = av.x; As[acol+1][arow] = av.y;
    As[acol+2][arow] = av.z; As[acol+3][arow] = av.w;
    float4 bv = *(const float4*)(Wih + (size_t)(k0+brow)*N + n0 + bcol);
    *(float4*)&Bs[brow][bcol] = bv;
    __syncthreads();
    #pragma unroll
    for (int kk = 0; kk < 16; kk++){
      float4 am = *(float4*)&As[kk][tr<<2];
      float4 bn = *(float4*)&Bs[kk][tc<<2];
      acc[0][0]+=am.x*bn.x; acc[0][1]+=am.x*bn.y; acc[0][2]+=am.x*bn.z; acc[0][3]+=am.x*bn.w;
      acc[1][0]+=am.y*bn.x; acc[1][1]+=am.y*bn.y; acc[1][2]+=am.y*bn.z; acc[1][3]+=am.y*bn.w;
      acc[2][0]+=am.z*bn.x; acc[2][1]+=am.z*bn.y; acc[2][2]+=am.z*bn.z; acc[2][3]+=am.z*bn.w;
      acc[3][0]+=am.w*bn.x; acc[3][1]+=am.w*bn.y; acc[3][2]+=am.w*bn.z; acc[3][3]+=am.w*bn.w;
    }
    __syncthreads();
  }
  #pragma unroll
  for (int i = 0; i < 4; i++){
    int mrow = m0 + (tr<<2) + i;
    #pragma unroll
    for (int j = 0; j < 4; j++){
      int ncol = n0 + (tc<<2) + j;
      g_gx[(size_t)mrow*N + ncol] = acc[i][j] + bias[ncol];
    }
  }
}

// ---------------- persistent LSTM: all 64 steps in one kernel ---------------
// grid = 128 CTAs = 4 row-tiles(64) x 32 hidden-slices(16). 256 threads.
// SMEM: Ws[512][64] (gate cols for this hidden slice, resident) + As dbl buf.
#define AS_PAD 66
#define SMEM_LSTM ((512*64 + 2*32*AS_PAD) * 4)

extern __shared__ float smem_dyn[];

__global__ void __launch_bounds__(256) k_lstm_persist(const float* __restrict__ Whh){
  float* Ws = smem_dyn;                 // [k][jh*4+g]
  float* As = smem_dyn + 512*64;        // [2][32][AS_PAD] : [k][row] transposed
  int tid = threadIdx.x;
  int hs = blockIdx.x & 31;             // hidden slice
  int mt = blockIdx.x >> 5;             // row tile
  int m0 = mt << 6;

  // load Whh slice into SMEM once: Ws[k][jh*4+g] = Whh[k][g*512 + hs*16 + jh]
  {
    int jh = tid & 15, g = (tid>>4)&3, kq = tid>>6;   // kq 0..3
    for (int k = kq; k < 512; k += 4)
      Ws[k*64 + jh*4 + g] = Whh[(size_t)k*G4 + g*512 + hs*16 + jh];
  }
  __syncthreads();

  int rg = tid >> 4;            // rowgroup 0..15 (4 rows each)
  int jh = tid & 15;
  int jglob = hs*16 + jh;
  int r0 = m0 + (rg<<2);

  // staging map
  int srow  = tid >> 3;         // 0..31
  int skoff = (tid & 7) << 2;   // 0..28

  float cc[4] = {0.f,0.f,0.f,0.f};   // cell state lives in registers

  for (int t = 0; t < LT; t++){
    const float* hprev = g_h[t & 1];
    float*       hnext = g_h[(t+1) & 1];

    u64 acc0p0=0, acc0p1=0, acc1p0=0, acc1p1=0;
    u64 acc2p0=0, acc2p1=0, acc3p0=0, acc3p1=0;

    const float* hr0 = hprev + (size_t)(m0+srow)*Hdim + skoff;
    const float* hr1 = hprev + (size_t)(m0+srow+32)*Hdim + skoff;
    float4 p0 = __ldcg((const float4*)hr0);
    float4 p1 = __ldcg((const float4*)hr1);
    int buf = 0;
    for (int k0 = 0; k0 < Hdim; k0 += 32){
      float* A = As + buf*(32*AS_PAD);
      A[(skoff+0)*AS_PAD + srow] = p0.x;
      A[(skoff+1)*AS_PAD + srow] = p0.y;
      A[(skoff+2)*AS_PAD + srow] = p0.z;
      A[(skoff+3)*AS_PAD + srow] = p0.w;
      A[(skoff+0)*AS_PAD + srow+32] = p1.x;
      A[(skoff+1)*AS_PAD + srow+32] = p1.y;
      A[(skoff+2)*AS_PAD + srow+32] = p1.z;
      A[(skoff+3)*AS_PAD + srow+32] = p1.w;
      __syncthreads();
      if (k0 + 32 < Hdim){
        p0 = __ldcg((const float4*)(hr0 + k0 + 32));
        p1 = __ldcg((const float4*)(hr1 + k0 + 32));
      }
      const float* Wk = Ws + (size_t)k0*64 + (jh<<2);
      #pragma unroll
      for (int kk = 0; kk < 32; kk++){
        const float* Ak = A + kk*AS_PAD + (rg<<2);
        u64 a01 = *(const u64*)(Ak);
        u64 a23 = *(const u64*)(Ak + 2);
        float4 b = *(const float4*)(Wk + kk*64);
        u64 b0 = pk2(b.x,b.x), b1 = pk2(b.y,b.y);
        u64 b2 = pk2(b.z,b.z), b3 = pk2(b.w,b.w);
        acc0p0 = fma2(a01,b0,acc0p0); acc0p1 = fma2(a23,b0,acc0p1);
        acc1p0 = fma2(a01,b1,acc1p0); acc1p1 = fma2(a23,b1,acc1p1);
        acc2p0 = fma2(a01,b2,acc2p0); acc2p1 = fma2(a23,b2,acc2p1);
        acc3p0 = fma2(a01,b3,acc3p0); acc3p1 = fma2(a23,b3,acc3p1);
      }
      __syncthreads();
      buf ^= 1;
    }

    // epilogue: activations for 4 rows x hidden col jglob
    float iv[4], fv[4], gv[4], ov[4];
    upk2(acc0p0, iv[0], iv[1]); upk2(acc0p1, iv[2], iv[3]);
    upk2(acc1p0, fv[0], fv[1]); upk2(acc1p1, fv[2], fv[3]);
    upk2(acc2p0, gv[0], gv[1]); upk2(acc2p1, gv[2], gv[3]);
    upk2(acc3p0, ov[0], ov[1]); upk2(acc3p1, ov[2], ov[3]);
    const float* gx = g_gx + (size_t)t*NB*G4;
    float* ys = g_ys + (size_t)t*NB*Hdim;
    #pragma unroll
    for (int rr = 0; rr < 4; rr++){
      int n = r0 + rr;
      const float* gb = gx + (size_t)n*G4 + jglob;
      float i_ = iv[rr] + gb[0];
      float f_ = fv[rr] + gb[512];
      float g_ = gv[rr] + gb[1024];
      float o_ = ov[rr] + gb[1536];
      float c_ = sigmf(f_)*cc[rr] + sigmf(i_)*tanhf(g_);
      float h_ = sigmf(o_)*tanhf(c_);
      cc[rr] = c_;
      hnext[(size_t)n*Hdim + jglob] = h_;
      ys   [(size_t)n*Hdim + jglob] = h_;
    }

    // grid barrier (skip after last step)
    if (t < LT-1){
      __threadfence();
      __syncthreads();
      if (tid == 0){
        atomicAdd(&g_barrier, 1u);
        unsigned target = (unsigned)(t+1) * LSTM_GRID;
        volatile unsigned* vb = &g_barrier;
        while (*vb < target) { }
      }
      __syncthreads();
    }
  }
}

// ---------------- GNN: build nodes ------------------------------------------
__global__ void k_nodes(){
  int b = blockIdx.x, h = threadIdx.x;
  const float* last = g_ys + (size_t)(LT-1)*NB*Hdim;
  float s = 0.0f;
  for (int u = 0; u < UU; u++){
    float v = last[(size_t)(b*UU + u)*Hdim + h];
    g_nodes[(size_t)(b*NNODE + u)*Hdim + h] = v;
    s += v;
  }
  g_nodes[(size_t)(b*NNODE + UU)*Hdim + h] = s * (1.0f/UU);
}

// ---------------- per-edge message ------------------------------------------
__global__ void __launch_bounds__(256) k_msg(const int* __restrict__ edge_src,
                                             const int* __restrict__ rels,
                                             const float* __restrict__ Wrel){
  int be = blockIdx.x;
  int b = be >> 7;
  int rel = rels[be];
  int es  = edge_src[be];
  __shared__ float xs[Hdim];
  int tid = threadIdx.x;
  xs[tid]     = g_nodes[(size_t)(b*NNODE + es)*Hdim + tid];
  xs[tid+256] = g_nodes[(size_t)(b*NNODE + es)*Hdim + tid + 256];
  __syncthreads();
  const float* W = Wrel + (size_t)rel*Hdim*Hdim;
  float a0 = 0.0f, a1 = 0.0f;
  for (int k = 0; k < Hdim; k++){
    float xv = xs[k];
    a0 += xv * W[(size_t)k*Hdim + tid];
    a1 += xv * W[(size_t)k*Hdim + tid + 256];
  }
  g_msg[(size_t)be*Hdim + tid]       = a0;
  g_msg[(size_t)be*Hdim + tid + 256] = a1;
}

// ---------------- deterministic segment-sum ---------------------------------
__global__ void k_agg(const int* __restrict__ edge_dst){
  int bd = blockIdx.x;
  int b = bd / NNODE, d = bd % NNODE;
  int h = threadIdx.x;
  float a = 0.0f;
  for (int e = 0; e < EE; e++){
    if (edge_dst[b*EE + e] == d)
      a += g_msg[(size_t)(b*EE + e)*Hdim + h];
  }
  g_agg[(size_t)bd*Hdim + h] = a;
}

// ---------------- GNN output/gate fusion ------------------------------------
__global__ void __launch_bounds__(256) k_gnn(const float* __restrict__ Wself,
                                             const float* __restrict__ bg,
                                             const float* __restrict__ Wg1,
                                             const float* __restrict__ Wg2){
  int bd = blockIdx.x;
  __shared__ float nd[Hdim], ag[Hdim];
  int tid = threadIdx.x;
  nd[tid]     = g_nodes[(size_t)bd*Hdim + tid];
  nd[tid+256] = g_nodes[(size_t)bd*Hdim + tid + 256];
  ag[tid]     = g_agg[(size_t)bd*Hdim + tid];
  ag[tid+256] = g_agg[(size_t)bd*Hdim + tid + 256];
  __syncthreads();
  for (int jo = 0; jo < 2; jo++){
    int j = tid + jo*256;
    float s1 = 0.0f, s2 = 0.0f, s3 = 0.0f;
    for (int k = 0; k < Hdim; k++){
      float nv = nd[k], av = ag[k];
      s1 += nv * Wself[(size_t)k*Hdim + j];
      s2 += nv * Wg1  [(size_t)k*Hdim + j];
      s3 += av * Wg2  [(size_t)k*Hdim + j];
    }
    float outv = s1 + ag[j] + bg[j];
    outv = outv > 0.0f ? outv : 0.0f;
    float gate = sigmf(s2 + s3);
    g_new[(size_t)bd*Hdim + j] = gate*outv + (1.0f - gate)*nd[j];
  }
}

// ---------------- output writers --------------------------------------------
__global__ void k_out_small(float* __restrict__ dout, const int* __restrict__ lengths){
  int i = blockIdx.x*blockDim.x + threadIdx.x;
  if (i < 4096){
    int b = i >> 9, h = i & 511;
    float v = g_new[(size_t)(b*NNODE + UU)*Hdim + h];
    dout[OFF_ENCH + i] = v;
    dout[OFF_ENCC + i] = v;
  }
  if (i < 8){
    float lv = (float)lengths[i];
    dout[OFF_LEN1 + i] = lv;
    dout[OFF_LEN2 + i] = lv;
  }
  dout[OFF_HIER + i] = (float)LT;
}

__global__ void k_big_out(float* __restrict__ dout){
  size_t i = (size_t)blockIdx.x*blockDim.x + threadIdx.x;
  if (i >= (size_t)SS*BB*Hdim) return;
  int h = (int)(i & 511);
  int b = (int)((i >> 9) & 7);
  int s = (int)(i >> 12);
  int t = s & 63, u = s >> 6;
  dout[OFF_MB  + i] = g_ys[((size_t)t*NB + b*UU + u)*Hdim + h];
  dout[OFF_MBU + i] = g_new[(size_t)(b*NNODE + u)*Hdim + h];
}

// ---------------- driver -----------------------------------------------------
extern "C" void kernel_launch(void* const* d_in, const int* in_sizes, int n_in,
                              void* d_out, int out_size){
  const int*   src      = (const int*)  d_in[0];
  const int*   speaker  = (const int*)  d_in[2];
  const int*   lengths  = (const int*)  d_in[3];
  const int*   edge_src = (const int*)  d_in[4];
  const int*   edge_dst = (const int*)  d_in[5];
  const int*   rels     = (const int*)  d_in[6];
  const float* emb      = (const float*)d_in[7];
  const float* spkt     = (const float*)d_in[8];
  const float* Wih      = (const float*)d_in[9];
  const float* Whh      = (const float*)d_in[10];
  const float* bl       = (const float*)d_in[11];
  const float* Wrel     = (const float*)d_in[12];
  const float* Wself    = (const float*)d_in[13];
  const float* bg       = (const float*)d_in[14];
  const float* Wg1      = (const float*)d_in[15];
  const float* Wg2      = (const float*)d_in[16];
  float* dout = (float*)d_out;

  cudaFuncSetAttribute(k_lstm_persist, cudaFuncAttributeMaxDynamicSharedMemorySize, SMEM_LSTM);

  k_zero<<<512, 256>>>();
  k_embed<<<LT*NB, 256>>>(src, speaker, emb, spkt);
  k_gx_gemm<<<dim3(G4/64, (LT*NB)/64), 256>>>(Wih, bl);
  k_lstm_persist<<<LSTM_GRID, 256, SMEM_LSTM>>>(Whh);
  k_nodes<<<BB, 512>>>();
  k_msg<<<BB*EE, 256>>>(edge_src, rels, Wrel);
  k_agg<<<BB*NNODE, 512>>>(edge_dst);
  k_gnn<<<BB*NNODE, 256>>>(Wself, bg, Wg1, Wg2);
  k_out_small<<<64, 256>>>(dout, lengths);
  k_big_out<<<32768, 256>>>(dout);
}

// round 5
// speedup vs baseline: 2.3633x; 1.1807x over previous
#include <cuda_runtime.h>
#include <math.h>

#define Hdim 512
#define G4   2048
#define NB   256      // B*U lstm lanes
#define LT   64       // timesteps
#define BB   8
#define UU   32
#define SS   2048
#define EE   128
#define NNODE 33      // U+1
#define LSTM_GRID 128

typedef unsigned long long u64;

__device__ __forceinline__ u64 pk2(float lo, float hi){
  u64 r; asm("mov.b64 %0, {%1,%2};" : "=l"(r) : "r"(__float_as_uint(lo)), "r"(__float_as_uint(hi))); return r;
}
__device__ __forceinline__ u64 fma2(u64 a, u64 b, u64 c){
  u64 d; asm("fma.rn.f32x2 %0, %1, %2, %3;" : "=l"(d) : "l"(a), "l"(b), "l"(c)); return d;
}
__device__ __forceinline__ void upk2(u64 v, float& lo, float& hi){
  unsigned l_, h_; asm("mov.b64 {%0,%1}, %2;" : "=r"(l_), "=r"(h_) : "l"(v));
  lo = __uint_as_float(l_); hi = __uint_as_float(h_);
}

// ---------------- scratch (device globals; no allocations allowed) ----------
__device__ float g_x  [(size_t)LT*NB*Hdim];
__device__ float g_gx [(size_t)LT*NB*G4];
__device__ float g_ys [(size_t)LT*NB*Hdim];
__device__ float g_h  [2][NB*Hdim];
__device__ float g_nodes[BB*NNODE*Hdim];
__device__ float g_msg  [(size_t)BB*EE*Hdim];
__device__ float g_agg  [BB*NNODE*Hdim];
__device__ float g_new  [BB*NNODE*Hdim];
__device__ unsigned g_bar4[4];

// ---------------- output offsets (pytree flatten order) ---------------------
#define OFF_ENCH 0
#define OFF_ENCC 4096
#define OFF_MB   8192
#define OFF_LEN1 (8192 + 8388608)
#define OFF_MBU  (OFF_LEN1 + 8)
#define OFF_LEN2 (OFF_MBU + 8388608)
#define OFF_HIER (OFF_LEN2 + 8)

__device__ __forceinline__ float sigmf(float x){ return 1.0f/(1.0f+expf(-x)); }

// ---------------- init: zero h0, barriers ------------------------------------
__global__ void k_zero(){
  int i = blockIdx.x*blockDim.x + threadIdx.x;
  if (i < NB*Hdim){ g_h[0][i] = 0.0f; }
  if (i < 4) g_bar4[i] = 0u;
}

// ---------------- embedding gather -----------------------------------------
__global__ void k_embed(const int* __restrict__ src, const int* __restrict__ speaker,
                        const float* __restrict__ emb, const float* __restrict__ spkt){
  int row = blockIdx.x;            // t*256 + n
  int t = row >> 8, n = row & 255;
  int b = n >> 5, u = n & 31;
  int s = u*LT + t;
  int w  = src[s*BB + b];
  int sp = speaker[b*SS + s];
  const float* er = emb  + (size_t)w  * Hdim;
  const float* sr = spkt + (size_t)sp * Hdim;
  float* xr = g_x + (size_t)row * Hdim;
  for (int h = threadIdx.x; h < Hdim; h += blockDim.x)
    xr[h] = er[h] + sr[h];
}

// ---------------- Gx = x @ W_ih + b ; M=16384 N=2048 K=512 ------------------
// 128x64 tile, 256 threads, 8 rows x 4 cols per thread via f32x2.
#define GX_PAD 130
__global__ void __launch_bounds__(256) k_gx_gemm(const float* __restrict__ Wih,
                                                 const float* __restrict__ bias){
  __shared__ float As[2][16][GX_PAD];  // [k][m], transposed, pad 130 (conflict-free)
  __shared__ float Bs[2][16][64];      // [k][n]
  int tid = threadIdx.x;
  int m0 = blockIdx.y*128, n0 = blockIdx.x*64;
  int tr = tid>>4, tc = tid&15;          // output: rows tr*8..+7, cols tc*4..+3
  // A staging: 2 rounds, 4 lanes/row (float4): row = rr*64 + (tid>>2), koff=(tid&3)*4
  int s_arow = tid>>2, s_ak = (tid&3)<<2;
  // B staging: k = tid>>4, col = (tid&15)*4
  int s_bk = tid>>4, s_bn = (tid&15)<<2;

  const float* Ap = g_x + (size_t)(m0 + s_arow)*Hdim + s_ak;
  const float* Bp = Wih + (size_t)s_bk*G4 + n0 + s_bn;

  float4 ra0 = *(const float4*)Ap;
  float4 ra1 = *(const float4*)(Ap + (size_t)64*Hdim);
  float4 rb  = *(const float4*)Bp;

  u64 acc[4][4];   // [rowpair][col]
  #pragma unroll
  for (int r=0;r<4;r++){ acc[r][0]=0; acc[r][1]=0; acc[r][2]=0; acc[r][3]=0; }

  int buf = 0;
  for (int k0 = 0; k0 < Hdim; k0 += 16){
    As[buf][s_ak+0][s_arow]    = ra0.x; As[buf][s_ak+1][s_arow]    = ra0.y;
    As[buf][s_ak+2][s_arow]    = ra0.z; As[buf][s_ak+3][s_arow]    = ra0.w;
    As[buf][s_ak+0][s_arow+64] = ra1.x; As[buf][s_ak+1][s_arow+64] = ra1.y;
    As[buf][s_ak+2][s_arow+64] = ra1.z; As[buf][s_ak+3][s_arow+64] = ra1.w;
    *(float4*)&Bs[buf][s_bk][s_bn] = rb;
    __syncthreads();
    if (k0 + 16 < Hdim){
      Ap += 16; Bp += (size_t)16*G4;
      ra0 = *(const float4*)Ap;
      ra1 = *(const float4*)(Ap + (size_t)64*Hdim);
      rb  = *(const float4*)Bp;
    }
    #pragma unroll
    for (int kk = 0; kk < 16; kk++){
      const float* Ak = &As[buf][kk][tr<<3];
      u64 a0 = *(const u64*)(Ak);
      u64 a1 = *(const u64*)(Ak+2);
      u64 a2 = *(const u64*)(Ak+4);
      u64 a3 = *(const u64*)(Ak+6);
      float4 b = *(const float4*)&Bs[buf][kk][tc<<2];
      u64 b0 = pk2(b.x,b.x), b1 = pk2(b.y,b.y), b2 = pk2(b.z,b.z), b3 = pk2(b.w,b.w);
      acc[0][0]=fma2(a0,b0,acc[0][0]); acc[0][1]=fma2(a0,b1,acc[0][1]);
      acc[0][2]=fma2(a0,b2,acc[0][2]); acc[0][3]=fma2(a0,b3,acc[0][3]);
      acc[1][0]=fma2(a1,b0,acc[1][0]); acc[1][1]=fma2(a1,b1,acc[1][1]);
      acc[1][2]=fma2(a1,b2,acc[1][2]); acc[1][3]=fma2(a1,b3,acc[1][3]);
      acc[2][0]=fma2(a2,b0,acc[2][0]); acc[2][1]=fma2(a2,b1,acc[2][1]);
      acc[2][2]=fma2(a2,b2,acc[2][2]); acc[2][3]=fma2(a2,b3,acc[2][3]);
      acc[3][0]=fma2(a3,b0,acc[3][0]); acc[3][1]=fma2(a3,b1,acc[3][1]);
      acc[3][2]=fma2(a3,b2,acc[3][2]); acc[3][3]=fma2(a3,b3,acc[3][3]);
    }
    buf ^= 1;
  }
  int mrow = m0 + (tr<<3);
  int ncol = n0 + (tc<<2);
  float b0 = bias[ncol], b1 = bias[ncol+1], b2 = bias[ncol+2], b3 = bias[ncol+3];
  #pragma unroll
  for (int rp = 0; rp < 4; rp++){
    float r0c0,r1c0,r0c1,r1c1,r0c2,r1c2,r0c3,r1c3;
    upk2(acc[rp][0], r0c0, r1c0);
    upk2(acc[rp][1], r0c1, r1c1);
    upk2(acc[rp][2], r0c2, r1c2);
    upk2(acc[rp][3], r0c3, r1c3);
    *(float4*)&g_gx[(size_t)(mrow + rp*2    )*G4 + ncol] = make_float4(r0c0+b0, r0c1+b1, r0c2+b2, r0c3+b3);
    *(float4*)&g_gx[(size_t)(mrow + rp*2 + 1)*G4 + ncol] = make_float4(r1c0+b0, r1c1+b1, r1c2+b2, r1c3+b3);
  }
}

// ---------------- persistent LSTM: all 64 steps in one kernel ---------------
// grid = 128 CTAs = 4 row-tiles(64) x 32 hidden-slices(16). 256 threads.
#define AS_PAD 66
#define SMEM_LSTM ((512*64 + 2*32*AS_PAD) * 4)

extern __shared__ float smem_dyn[];

__global__ void __launch_bounds__(256) k_lstm_persist(const float* __restrict__ Whh){
  float* Ws = smem_dyn;                 // [k][jh*4+g]
  float* As = smem_dyn + 512*64;        // [2][32][AS_PAD] : [k][row] transposed
  int tid = threadIdx.x;
  int hs = blockIdx.x & 31;             // hidden slice
  int mt = blockIdx.x >> 5;             // row tile
  int m0 = mt << 6;

  // load Whh slice into SMEM once: Ws[k][jh*4+g] = Whh[k][g*512 + hs*16 + jh]
  {
    int jh = tid & 15, g = (tid>>4)&3, kq = tid>>6;   // kq 0..3
    for (int k = kq; k < 512; k += 4)
      Ws[k*64 + jh*4 + g] = Whh[(size_t)k*G4 + g*512 + hs*16 + jh];
  }
  __syncthreads();

  int rg = tid >> 4;            // rowgroup 0..15 (4 rows each)
  int jh = tid & 15;
  int jglob = hs*16 + jh;
  int r0 = m0 + (rg<<2);

  // staging map
  int srow  = tid >> 3;         // 0..31
  int skoff = (tid & 7) << 2;   // 0..28

  float cc[4] = {0.f,0.f,0.f,0.f};   // cell state lives in registers

  for (int t = 0; t < LT; t++){
    const float* hprev = g_h[t & 1];
    float*       hnext = g_h[(t+1) & 1];

    // prefetch epilogue gx values (latency hidden under the k-loop)
    float pi[4], pf[4], pg[4], po[4];
    {
      const float* gx = g_gx + (size_t)t*NB*G4;
      #pragma unroll
      for (int rr = 0; rr < 4; rr++){
        const float* gb = gx + (size_t)(r0+rr)*G4 + jglob;
        pi[rr] = __ldcg(gb);
        pf[rr] = __ldcg(gb + 512);
        pg[rr] = __ldcg(gb + 1024);
        po[rr] = __ldcg(gb + 1536);
      }
    }

    u64 acc0p0=0, acc0p1=0, acc1p0=0, acc1p1=0;
    u64 acc2p0=0, acc2p1=0, acc3p0=0, acc3p1=0;

    const float* hr0 = hprev + (size_t)(m0+srow)*Hdim + skoff;
    const float* hr1 = hprev + (size_t)(m0+srow+32)*Hdim + skoff;
    float4 p0 = __ldcg((const float4*)hr0);
    float4 p1 = __ldcg((const float4*)hr1);
    int buf = 0;
    for (int k0 = 0; k0 < Hdim; k0 += 32){
      float* A = As + buf*(32*AS_PAD);
      A[(skoff+0)*AS_PAD + srow] = p0.x;
      A[(skoff+1)*AS_PAD + srow] = p0.y;
      A[(skoff+2)*AS_PAD + srow] = p0.z;
      A[(skoff+3)*AS_PAD + srow] = p0.w;
      A[(skoff+0)*AS_PAD + srow+32] = p1.x;
      A[(skoff+1)*AS_PAD + srow+32] = p1.y;
      A[(skoff+2)*AS_PAD + srow+32] = p1.z;
      A[(skoff+3)*AS_PAD + srow+32] = p1.w;
      __syncthreads();              // single barrier per chunk (double buffer)
      if (k0 + 32 < Hdim){
        p0 = __ldcg((const float4*)(hr0 + k0 + 32));
        p1 = __ldcg((const float4*)(hr1 + k0 + 32));
      }
      const float* Wk = Ws + (size_t)k0*64 + (jh<<2);
      #pragma unroll
      for (int kk = 0; kk < 32; kk++){
        const float* Ak = A + kk*AS_PAD + (rg<<2);
        u64 a01 = *(const u64*)(Ak);
        u64 a23 = *(const u64*)(Ak + 2);
        float4 b = *(const float4*)(Wk + kk*64);
        u64 b0 = pk2(b.x,b.x), b1 = pk2(b.y,b.y);
        u64 b2 = pk2(b.z,b.z), b3 = pk2(b.w,b.w);
        acc0p0 = fma2(a01,b0,acc0p0); acc0p1 = fma2(a23,b0,acc0p1);
        acc1p0 = fma2(a01,b1,acc1p0); acc1p1 = fma2(a23,b1,acc1p1);
        acc2p0 = fma2(a01,b2,acc2p0); acc2p1 = fma2(a23,b2,acc2p1);
        acc3p0 = fma2(a01,b3,acc3p0); acc3p1 = fma2(a23,b3,acc3p1);
      }
      buf ^= 1;
    }

    // epilogue: activations for 4 rows x hidden col jglob
    float iv[4], fv[4], gv[4], ov[4];
    upk2(acc0p0, iv[0], iv[1]); upk2(acc0p1, iv[2], iv[3]);
    upk2(acc1p0, fv[0], fv[1]); upk2(acc1p1, fv[2], fv[3]);
    upk2(acc2p0, gv[0], gv[1]); upk2(acc2p1, gv[2], gv[3]);
    upk2(acc3p0, ov[0], ov[1]); upk2(acc3p1, ov[2], ov[3]);
    float* ys = g_ys + (size_t)t*NB*Hdim;
    #pragma unroll
    for (int rr = 0; rr < 4; rr++){
      int n = r0 + rr;
      float i_ = iv[rr] + pi[rr];
      float f_ = fv[rr] + pf[rr];
      float g_ = gv[rr] + pg[rr];
      float o_ = ov[rr] + po[rr];
      float c_ = sigmf(f_)*cc[rr] + sigmf(i_)*tanhf(g_);
      float h_ = sigmf(o_)*tanhf(c_);
      cc[rr] = c_;
      hnext[(size_t)n*Hdim + jglob] = h_;
      ys   [(size_t)n*Hdim + jglob] = h_;
    }

    // group barrier over the 32 CTAs sharing this row-tile (skip after last)
    if (t < LT-1){
      __threadfence();
      __syncthreads();
      if (tid == 0){
        atomicAdd(&g_bar4[mt], 1u);
        unsigned target = (unsigned)(t+1) * 32u;
        volatile unsigned* vb = &g_bar4[mt];
        while (*vb < target) { }
      }
      __syncthreads();
    }
  }
}

// ---------------- GNN: build nodes ------------------------------------------
__global__ void k_nodes(){
  int b = blockIdx.x, h = threadIdx.x;
  const float* last = g_ys + (size_t)(LT-1)*NB*Hdim;
  float s = 0.0f;
  for (int u = 0; u < UU; u++){
    float v = last[(size_t)(b*UU + u)*Hdim + h];
    g_nodes[(size_t)(b*NNODE + u)*Hdim + h] = v;
    s += v;
  }
  g_nodes[(size_t)(b*NNODE + UU)*Hdim + h] = s * (1.0f/UU);
}

// ---------------- per-edge message ------------------------------------------
__global__ void __launch_bounds__(256) k_msg(const int* __restrict__ edge_src,
                                             const int* __restrict__ rels,
                                             const float* __restrict__ Wrel){
  int be = blockIdx.x;
  int b = be >> 7;
  int rel = rels[be];
  int es  = edge_src[be];
  __shared__ float xs[Hdim];
  int tid = threadIdx.x;
  xs[tid]     = g_nodes[(size_t)(b*NNODE + es)*Hdim + tid];
  xs[tid+256] = g_nodes[(size_t)(b*NNODE + es)*Hdim + tid + 256];
  __syncthreads();
  const float* W = Wrel + (size_t)rel*Hdim*Hdim;
  float a0 = 0.0f, a1 = 0.0f;
  for (int k = 0; k < Hdim; k++){
    float xv = xs[k];
    a0 += xv * W[(size_t)k*Hdim + tid];
    a1 += xv * W[(size_t)k*Hdim + tid + 256];
  }
  g_msg[(size_t)be*Hdim + tid]       = a0;
  g_msg[(size_t)be*Hdim + tid + 256] = a1;
}

// ---------------- deterministic segment-sum ---------------------------------
__global__ void k_agg(const int* __restrict__ edge_dst){
  int bd = blockIdx.x;
  int b = bd / NNODE, d = bd % NNODE;
  int h = threadIdx.x;
  float a = 0.0f;
  for (int e = 0; e < EE; e++){
    if (edge_dst[b*EE + e] == d)
      a += g_msg[(size_t)(b*EE + e)*Hdim + h];
  }
  g_agg[(size_t)bd*Hdim + h] = a;
}

// ---------------- GNN output/gate fusion ------------------------------------
__global__ void __launch_bounds__(256) k_gnn(const float* __restrict__ Wself,
                                             const float* __restrict__ bg,
                                             const float* __restrict__ Wg1,
                                             const float* __restrict__ Wg2){
  int bd = blockIdx.x;
  __shared__ float nd[Hdim], ag[Hdim];
  int tid = threadIdx.x;
  nd[tid]     = g_nodes[(size_t)bd*Hdim + tid];
  nd[tid+256] = g_nodes[(size_t)bd*Hdim + tid + 256];
  ag[tid]     = g_agg[(size_t)bd*Hdim + tid];
  ag[tid+256] = g_agg[(size_t)bd*Hdim + tid + 256];
  __syncthreads();
  for (int jo = 0; jo < 2; jo++){
    int j = tid + jo*256;
    float s1 = 0.0f, s2 = 0.0f, s3 = 0.0f;
    for (int k = 0; k < Hdim; k++){
      float nv = nd[k], av = ag[k];
      s1 += nv * Wself[(size_t)k*Hdim + j];
      s2 += nv * Wg1  [(size_t)k*Hdim + j];
      s3 += av * Wg2  [(size_t)k*Hdim + j];
    }
    float outv = s1 + ag[j] + bg[j];
    outv = outv > 0.0f ? outv : 0.0f;
    float gate = sigmf(s2 + s3);
    g_new[(size_t)bd*Hdim + j] = gate*outv + (1.0f - gate)*nd[j];
  }
}

// ---------------- output writers --------------------------------------------
__global__ void k_out_small(float* __restrict__ dout, const int* __restrict__ lengths){
  int i = blockIdx.x*blockDim.x + threadIdx.x;
  if (i < 4096){
    int b = i >> 9, h = i & 511;
    float v = g_new[(size_t)(b*NNODE + UU)*Hdim + h];
    dout[OFF_ENCH + i] = v;
    dout[OFF_ENCC + i] = v;
  }
  if (i < 8){
    float lv = (float)lengths[i];
    dout[OFF_LEN1 + i] = lv;
    dout[OFF_LEN2 + i] = lv;
  }
  dout[OFF_HIER + i] = (float)LT;
}

__global__ void k_big_out(float* __restrict__ dout){
  size_t i = (size_t)blockIdx.x*blockDim.x + threadIdx.x;
  if (i >= (size_t)SS*BB*Hdim) return;
  int h = (int)(i & 511);
  int b = (int)((i >> 9) & 7);
  int s = (int)(i >> 12);
  int t = s & 63, u = s >> 6;
  dout[OFF_MB  + i] = g_ys[((size_t)t*NB + b*UU + u)*Hdim + h];
  dout[OFF_MBU + i] = g_new[(size_t)(b*NNODE + u)*Hdim + h];
}

// ---------------- driver -----------------------------------------------------
extern "C" void kernel_launch(void* const* d_in, const int* in_sizes, int n_in,
                              void* d_out, int out_size){
  const int*   src      = (const int*)  d_in[0];
  const int*   speaker  = (const int*)  d_in[2];
  const int*   lengths  = (const int*)  d_in[3];
  const int*   edge_src = (const int*)  d_in[4];
  const int*   edge_dst = (const int*)  d_in[5];
  const int*   rels     = (const int*)  d_in[6];
  const float* emb      = (const float*)d_in[7];
  const float* spkt     = (const float*)d_in[8];
  const float* Wih      = (const float*)d_in[9];
  const float* Whh      = (const float*)d_in[10];
  const float* bl       = (const float*)d_in[11];
  const float* Wrel     = (const float*)d_in[12];
  const float* Wself    = (const float*)d_in[13];
  const float* bg       = (const float*)d_in[14];
  const float* Wg1      = (const float*)d_in[15];
  const float* Wg2      = (const float*)d_in[16];
  float* dout = (float*)d_out;

  cudaFuncSetAttribute(k_lstm_persist, cudaFuncAttributeMaxDynamicSharedMemorySize, SMEM_LSTM);

  k_zero<<<512, 256>>>();
  k_embed<<<LT*NB, 256>>>(src, speaker, emb, spkt);
  k_gx_gemm<<<dim3(G4/64, (LT*NB)/128), 256>>>(Wih, bl);
  k_lstm_persist<<<LSTM_GRID, 256, SMEM_LSTM>>>(Whh);
  k_nodes<<<BB, 512>>>();
  k_msg<<<BB*EE, 256>>>(edge_src, rels, Wrel);
  k_agg<<<BB*NNODE, 512>>>(edge_dst);
  k_gnn<<<BB*NNODE, 256>>>(Wself, bg, Wg1, Wg2);
  k_out_small<<<64, 256>>>(dout, lengths);
  k_big_out<<<32768, 256>>>(dout);
}